// round 16
// baseline (speedup 1.0000x reference)
#include <cuda_runtime.h>
#include <cstdint>

#define N_NODES 100000
#define CH      128
#define N_REL   16
#define N_EDGES 200000
#define NW      17                        /* self + 16 relations */
#define TM      64                        /* tile rows */
#define NT      ((N_NODES + TM - 1) / TM) /* 1563 dst tiles */
#define NBK     (NT * N_REL * 8)          /* 200064 buckets (tile,rel,warp) */
#define HS      132                       /* hA row stride (floats) */
#define BS      136                       /* B smem row stride (floats) */
#define HSZ     (TM * HS)                 /* 8448 floats, single hA buffer */

// smem: hA | B-ring(2 x 32*BS)
#define SMF_B    HSZ
#define SMEM_FLOATS (SMF_B + 2 * 32 * BS)  /* 17152 floats = 68608 B -> 2 CTA/SM */
#define NSTG     (4 * NW)                 /* 68 B k-chunks */
#define NSB      ((NBK + 1023) / 1024)    /* 196 scan blocks */

// ---------------- device scratch (zero-init at load; self-cleaning) ------
__device__ unsigned      g_emeta[N_REL * N_EDGES];   // src | dl<<17 (sorted by bucket)
__device__ float         g_B[NW * CH * CH];          // tf32-rounded weights
__device__ int           g_deg[N_REL * N_NODES];     // zeroed by k_scanall after use
__device__ float         g_invdeg[N_REL * N_NODES];
__device__ int           g_bcnt[NBK];                // zeroed by k_scanall after use
__device__ int           g_boff[NBK + 1];
__device__ int           g_bfill[NBK];
__device__ int           g_bsum[256];
__device__ int           g_sflag[256];               // zeroed by k_fill2 after use

// ---------------- tf32 round ----------------
__device__ __forceinline__ unsigned f2tf(float f) {
    unsigned r;
    asm("cvt.rna.tf32.f32 %0, %1;" : "=r"(r) : "f"(f));
    return r;
}

// per-block dtype detection (jax int64/bool layout may vary); 256-thread blocks
__device__ __forceinline__ void detect_flags(const void* idx, const void* mask,
                                             bool& f64, bool& fm32) {
    __shared__ int s64, s32;
    if (threadIdx.x == 0) { s64 = 0; s32 = 0; }
    __syncthreads();
    const unsigned* w = (const unsigned*)idx;
    const unsigned char* mb = (const unsigned char*)mask;
    if (threadIdx.x < 128) { if (w[2 * threadIdx.x + 1] != 0u) atomicAdd(&s64, 1); }
    if (threadIdx.x < 192) {
        int i = (threadIdx.x / 3) * 4 + 1 + (threadIdx.x % 3);
        if (mb[i] != 0) atomicAdd(&s32, 1);
    }
    __syncthreads();
    f64 = (s64 < 8);
    fm32 = (s32 < 8);
}

__device__ __forceinline__ int rd_idx2(const void* p, long long i, bool f64) {
    return f64 ? (int)((const long long*)p)[i] : ((const int*)p)[i];
}
__device__ __forceinline__ int rd_mask2(const void* p, int i, bool fm32) {
    return fm32 ? (((const int*)p)[i] != 0) : (int)((const unsigned char*)p)[i];
}

// ---------------- L0: degree + bucket counting + weight rounding ---------
__global__ void k_deg2(const void* __restrict__ idx, const void* __restrict__ mask,
                       const float* __restrict__ selfw, const float* __restrict__ relw) {
    bool f64, fm32;
    detect_flags(idx, mask, f64, fm32);

    long long gid = ((long long)(blockIdx.y * gridDim.x + blockIdx.x)) * blockDim.x
                    + threadIdx.x;
    if (gid < (long long)NW * CH * CH) {
        int i = (int)gid;
        float v = (i < CH * CH) ? selfw[i] : relw[i - CH * CH];
        g_B[i] = __uint_as_float(f2tf(v));
    }

    int e = blockIdx.x * blockDim.x + threadIdx.x;
    int rel = blockIdx.y;
    if (e >= N_EDGES) return;
    if (!rd_mask2(mask, rel * N_EDGES + e, fm32)) return;
    int dst = rd_idx2(idx, (long long)rel * 2 * N_EDGES + N_EDGES + e, f64);
    atomicAdd(&g_deg[rel * N_NODES + dst], 1);
    int key = ((dst >> 6) * N_REL + rel) * 8 + ((dst >> 3) & 7);
    atomicAdd(&g_bcnt[key], 1);
}

// ---------------- L1: single-launch scan (parallel lookback) + invdeg ----
__global__ void k_scanall() {
    __shared__ int sh[1024];
    __shared__ int sred[256];
    int b = blockIdx.x;
    int i = b * 1024 + threadIdx.x;
    int v = (i < NBK) ? g_bcnt[i] : 0;
    sh[threadIdx.x] = v;
    __syncthreads();
    for (int off = 1; off < 1024; off <<= 1) {
        int t = (threadIdx.x >= off) ? sh[threadIdx.x - off] : 0;
        __syncthreads();
        sh[threadIdx.x] += t;
        __syncthreads();
    }
    int excl = sh[threadIdx.x] - v;   // block-local exclusive

    if (threadIdx.x == 1023) {
        g_bsum[b] = sh[1023];
        __threadfence();
        atomicExch(&g_sflag[b], 1);
    }
    // parallel lookback: thread t (<b) polls flag t, then tree-reduce
    if (threadIdx.x < 256) {
        int part = 0;
        if ((int)threadIdx.x < b) {
            while (atomicAdd(&g_sflag[threadIdx.x], 0) == 0) { }
            part = g_bsum[threadIdx.x];
        }
        sred[threadIdx.x] = part;
    }
    __syncthreads();
    for (int off = 128; off > 0; off >>= 1) {
        if (threadIdx.x < (unsigned)off) sred[threadIdx.x] += sred[threadIdx.x + off];
        __syncthreads();
    }
    int spref = sred[0];

    if (i < NBK) {
        int o = excl + spref;
        g_boff[i] = o;
        g_bfill[i] = o;
        g_bcnt[i] = 0;                         // self-clean for next replay
    }
    if (b == NSB - 1 && threadIdx.x == 1023)
        g_boff[NBK] = spref + sh[1023];        // total

    // invdeg + self-clean g_deg
    for (int j = i; j < N_REL * N_NODES; j += NSB * 1024) {
        int d = g_deg[j];
        g_invdeg[j] = d > 0 ? 1.0f / (float)d : 0.0f;
        g_deg[j] = 0;
    }
}

// ---------------- L2: fill sorted edge meta (+ zero scan flags) ----------
__global__ void k_fill2(const void* __restrict__ idx, const void* __restrict__ mask) {
    bool f64, fm32;
    detect_flags(idx, mask, f64, fm32);
    if (blockIdx.x == 0 && blockIdx.y == 0 && threadIdx.x < 256)
        g_sflag[threadIdx.x] = 0;              // self-clean for next replay
    int e = blockIdx.x * blockDim.x + threadIdx.x;
    int rel = blockIdx.y;
    if (e >= N_EDGES) return;
    if (!rd_mask2(mask, rel * N_EDGES + e, fm32)) return;
    int src = rd_idx2(idx, (long long)rel * 2 * N_EDGES + e, f64);
    int dst = rd_idx2(idx, (long long)rel * 2 * N_EDGES + N_EDGES + e, f64);
    int key = ((dst >> 6) * N_REL + rel) * 8 + ((dst >> 3) & 7);
    int pos = atomicAdd(&g_bfill[key], 1);
    g_emeta[pos] = (unsigned)src | ((unsigned)(dst & 63) << 17);
}

// ---------------- fused kernel helpers ----------------
__device__ __forceinline__ void cp16(float* sdst, const float* gsrc) {
    unsigned s = (unsigned)__cvta_generic_to_shared(sdst);
    asm volatile("cp.async.cg.shared.global [%0], [%1], 16;\n" :: "r"(s), "l"(gsrc));
}

// B stage s (weight s>>2, k-chunk s&3) into ring slot s&1. ALL 256 threads.
__device__ __forceinline__ void cp_stage(float* sB, int s, int tid) {
    if (s < NSTG) {
        int w = s >> 2, kt = s & 3;
        float* dB = sB + (s & 1) * 32 * BS;
        const float* src0 = g_B + (size_t)w * CH * CH + kt * 32 * CH;
#pragma unroll
        for (int i = 0; i < 4; i++) {
            int idx = tid + 256 * i;           // 1024 chunks of 16B
            int kr = idx >> 5, c4 = idx & 31;
            cp16(dB + kr * BS + c4 * 4, src0 + kr * CH + c4 * 4);
        }
    }
    asm volatile("cp.async.commit_group;\n");   // uniform group count
}

// warp tile 32x32: c[2][4][4]; A offset already includes wm*32 rows.
__device__ __forceinline__ void mma4h(float (*c)[4][4], const float* A, const float* Bsm,
                                      int lane) {
#pragma unroll
    for (int ks = 0; ks < 4; ks++) {
        unsigned a[2][4], b[4][2];
        int col = ks * 8 + (lane & 3);
        int r = lane >> 2;
#pragma unroll
        for (int mf = 0; mf < 2; mf++) {
            const float* Ap = A + (mf * 16 + r) * HS + col;
            a[mf][0] = f2tf(Ap[0]);
            a[mf][1] = f2tf(Ap[8 * HS]);
            a[mf][2] = f2tf(Ap[4]);
            a[mf][3] = f2tf(Ap[8 * HS + 4]);
        }
        int kr = ks * 8 + (lane & 3);
#pragma unroll
        for (int nf = 0; nf < 4; nf++) {
            const float* Bp = Bsm + kr * BS + nf * 8 + (lane >> 2);
            b[nf][0] = __float_as_uint(Bp[0]);       // pre-rounded tf32
            b[nf][1] = __float_as_uint(Bp[4 * BS]);
        }
#pragma unroll
        for (int mf = 0; mf < 2; mf++)
#pragma unroll
            for (int nf = 0; nf < 4; nf++)
                asm volatile(
                    "mma.sync.aligned.m16n8k8.row.col.f32.tf32.tf32.f32 "
                    "{%0,%1,%2,%3},{%4,%5,%6,%7},{%8,%9},{%0,%1,%2,%3};\n"
                    : "+f"(c[mf][nf][0]), "+f"(c[mf][nf][1]),
                      "+f"(c[mf][nf][2]), "+f"(c[mf][nf][3])
                    : "r"(a[mf][0]), "r"(a[mf][1]), "r"(a[mf][2]), "r"(a[mf][3]),
                      "r"(b[nf][0]), "r"(b[nf][1]));
    }
}

// gather warp wid: rows [wid*8, wid*8+8) = sum x[src]*invdeg, MLP-8 batches.
__device__ __forceinline__ void gather_rel(const float* __restrict__ x, float* hb,
                                           int tile, int rel, int wid, int lane) {
    float4 z = make_float4(0.f, 0.f, 0.f, 0.f);
    int r0 = wid * 8;
#pragma unroll
    for (int r = 0; r < 8; r++)
        ((float4*)(hb + (r0 + r) * HS))[lane] = z;

    int key = (tile * N_REL + rel) * 8 + wid;
    int beg = g_boff[key], end = g_boff[key + 1];
    const float* vd = g_invdeg + rel * N_NODES + tile * TM;
    for (int base = beg; base < end; base += 32) {
        unsigned m = 0;
        if (base + lane < end) m = g_emeta[base + lane];
        int n = min(32, end - base);
        int j = 0;
        for (; j + 8 <= n; j += 8) {                 // 8 independent 512B loads in flight
            int dl[8], sn[8];
            float sc[8];
            float4 v[8];
#pragma unroll
            for (int t = 0; t < 8; t++) {
                unsigned u = __shfl_sync(0xffffffffu, m, j + t);
                sn[t] = (int)(u & 0x1FFFFu);
                dl[t] = (int)(u >> 17);
            }
#pragma unroll
            for (int t = 0; t < 8; t++) sc[t] = __ldg(vd + dl[t]);
#pragma unroll
            for (int t = 0; t < 8; t++)
                v[t] = __ldg((const float4*)(x + (size_t)sn[t] * CH) + lane);
#pragma unroll
            for (int t = 0; t < 8; t++) {
                float4* hp = (float4*)(hb + dl[t] * HS) + lane;
                float4 hv = *hp;
                hv.x += v[t].x * sc[t]; hv.y += v[t].y * sc[t];
                hv.z += v[t].z * sc[t]; hv.w += v[t].w * sc[t];
                *hp = hv;
            }
        }
        for (; j + 4 <= n; j += 4) {                 // 4-batch tail
            int dl[4], sn[4];
            float sc[4];
            float4 v[4];
#pragma unroll
            for (int t = 0; t < 4; t++) {
                unsigned u = __shfl_sync(0xffffffffu, m, j + t);
                sn[t] = (int)(u & 0x1FFFFu);
                dl[t] = (int)(u >> 17);
            }
#pragma unroll
            for (int t = 0; t < 4; t++) sc[t] = __ldg(vd + dl[t]);
#pragma unroll
            for (int t = 0; t < 4; t++)
                v[t] = __ldg((const float4*)(x + (size_t)sn[t] * CH) + lane);
#pragma unroll
            for (int t = 0; t < 4; t++) {
                float4* hp = (float4*)(hb + dl[t] * HS) + lane;
                float4 hv = *hp;
                hv.x += v[t].x * sc[t]; hv.y += v[t].y * sc[t];
                hv.z += v[t].z * sc[t]; hv.w += v[t].w * sc[t];
                *hp = hv;
            }
        }
        for (; j < n; j++) {
            unsigned u = __shfl_sync(0xffffffffu, m, j);
            int sn = (int)(u & 0x1FFFFu);
            int dl = (int)(u >> 17);
            float s = __ldg(vd + dl);
            float4 v = __ldg((const float4*)(x + (size_t)sn * CH) + lane);
            float4* hp = (float4*)(hb + dl * HS) + lane;
            float4 hv = *hp;
            hv.x += v.x * s; hv.y += v.y * s; hv.z += v.z * s; hv.w += v.w * s;
            *hp = hv;
        }
    }
}

// ---------------- fused: MERGED phases — all 8 warps gather, then all mma
__global__ __launch_bounds__(256, 2) void k_fused(const float* __restrict__ x,
                                                  float* __restrict__ out) {
    extern __shared__ float sm[];
    float* hA = sm;                 // single buffer
    float* sB = sm + SMF_B;         // 2-slot ring
    int tid = threadIdx.x, wid = tid >> 5, lane = tid & 31;
    int tile = blockIdx.x, bM = tile * TM;
    int wm = wid >> 2, wn = wid & 3;   // 2x4 warp grid, warp tile 32x32

    float c[2][4][4];
#pragma unroll
    for (int i = 0; i < 2; i++)
#pragma unroll
        for (int j = 0; j < 4; j++)
#pragma unroll
            for (int k = 0; k < 4; k++) c[i][j][k] = 0.f;

    // prologue: self tile (weight 0) = x rows -> hA (8 rows per warp)
    {
        int r0 = wid * 8;
#pragma unroll
        for (int r = 0; r < 8; r++) {
            int rg = bM + r0 + r;
            float4 v = make_float4(0.f, 0.f, 0.f, 0.f);
            if (rg < N_NODES) v = __ldg((const float4*)(x + (size_t)rg * CH) + lane);
            ((float4*)(hA + (r0 + r) * HS))[lane] = v;
        }
    }
    cp_stage(sB, 0, tid);

#pragma unroll 1
    for (int w = 0; w < NW; w++) {
        const float* A = hA + (wm * 32) * HS;
#pragma unroll 1
        for (int kt = 0; kt < 4; kt++) {
            int s = w * 4 + kt;
            asm volatile("cp.async.wait_group 0;\n");  // stage s landed
            __syncthreads();   // kt=0: gather(w)/prologue writes visible; ring slot free
            cp_stage(sB, s + 1, tid);                  // prefetch into other slot
            mma4h(c, A + kt * 32, sB + (s & 1) * 32 * BS + wn * 32, lane);
        }
        if (w < NW - 1) {
            __syncthreads();   // all mma reads of hA done -> safe to overwrite
            gather_rel(x, hA, tile, w, wid, lane);     // B prefetch overlaps this
        }
    }

    // epilogue
#pragma unroll
    for (int mf = 0; mf < 2; mf++) {
        int r0 = bM + wm * 32 + mf * 16 + (lane >> 2);
#pragma unroll
        for (int nf = 0; nf < 4; nf++) {
            int cc = wn * 32 + nf * 8 + (lane & 3) * 2;
            if (r0 < N_NODES)
                *(float2*)(out + (size_t)r0 * CH + cc) =
                    make_float2(c[mf][nf][0], c[mf][nf][1]);
            if (r0 + 8 < N_NODES)
                *(float2*)(out + (size_t)(r0 + 8) * CH + cc) =
                    make_float2(c[mf][nf][2], c[mf][nf][3]);
        }
    }
}

// ---------------- launch: deg(0) scanall(1) fill(2) fused(3) -------------
extern "C" void kernel_launch(void* const* d_in, const int* in_sizes, int n_in,
                              void* d_out, int out_size) {
    const float* x     = (const float*)d_in[0];
    const void*  idx   = d_in[1];
    const void*  mask  = d_in[2];
    const float* selfw = (const float*)d_in[3];
    const float* relw  = (const float*)d_in[4];
    float* out = (float*)d_out;

    static int init = 0;
    size_t smem = SMEM_FLOATS * sizeof(float);   // 68608 B
    if (!init) {
        cudaFuncSetAttribute(k_fused, cudaFuncAttributeMaxDynamicSharedMemorySize, (int)smem);
        init = 1;
    }

    k_deg2<<<dim3((N_EDGES + 255) / 256, N_REL), 256>>>(idx, mask, selfw, relw);
    k_scanall<<<NSB, 1024>>>();
    k_fill2<<<dim3((N_EDGES + 255) / 256, N_REL), 256>>>(idx, mask);
    k_fused<<<NT, 256, smem>>>(x, out);
}

// round 17
// speedup vs baseline: 1.2190x; 1.2190x over previous
#include <cuda_runtime.h>
#include <cstdint>

#define N_NODES 100000
#define CH      128
#define N_REL   16
#define N_EDGES 200000
#define NW      17                        /* self + 16 relations */
#define TM      64                        /* tile rows */
#define NT      ((N_NODES + TM - 1) / TM) /* 1563 dst tiles */
#define NBK     (NT * N_REL * 4)          /* 100032 buckets (tile,rel,gwarp) */
#define HS      132                       /* hF row stride (f32) */
#define HF_FLOATS (TM * HS)               /* 8448 */
#define AROW    272                       /* hAh row stride bytes (136 f16) */
#define HAH_BYTES (TM * AROW)             /* 17408 per buffer */
#define HAH_FLOATS (2 * HAH_BYTES / 4)    /* 8704 */
#define BSU     136                       /* B smem row stride (u32 = f16x2) */
#define BSLOT   (16 * BSU)                /* 2176 u32 per stage */
#define SMEM_FLOATS (HF_FLOATS + HAH_FLOATS + 2 * BSLOT)  /* 21504 = 86016 B */
#define NSTG    (4 * NW)                  /* 68 B k-chunks */
#define NSB     98                        /* scan blocks */

// ---------------- device scratch (zero-init at load; self-cleaning) ------
__device__ unsigned      g_emeta[N_REL * N_EDGES];   // src | dl<<17 (sorted by bucket)
__device__ unsigned      g_Bh[NW * 64 * CH];         // f16x2-packed weights (k-pairs)
__device__ int           g_deg[N_REL * N_NODES];     // zeroed by k_scanall after use
__device__ float         g_invdeg[N_REL * N_NODES];
__device__ int           g_bcnt[NBK];                // zeroed by k_scanall after use
__device__ int           g_boff[NBK + 1];
__device__ int           g_bfill[NBK];
__device__ int           g_bsum[128];
__device__ int           g_sflag[128];               // zeroed by k_fill2 after use

// pack two f32 -> f16x2 (lo = first arg); validated in R11 (rel_err 2.93e-4)
__device__ __forceinline__ unsigned pack_h2(float lo, float hi) {
    unsigned r;
    asm("cvt.rn.f16x2.f32 %0, %1, %2;" : "=r"(r) : "f"(hi), "f"(lo));
    return r;
}

__device__ __forceinline__ uint32_t smem_u32(const void* p) {
    return (uint32_t)__cvta_generic_to_shared(p);
}

// per-block dtype detection (jax int64/bool layout may vary); 256-thread blocks
__device__ __forceinline__ void detect_flags(const void* idx, const void* mask,
                                             bool& f64, bool& fm32) {
    __shared__ int s64, s32;
    if (threadIdx.x == 0) { s64 = 0; s32 = 0; }
    __syncthreads();
    const unsigned* w = (const unsigned*)idx;
    const unsigned char* mb = (const unsigned char*)mask;
    if (threadIdx.x < 128) { if (w[2 * threadIdx.x + 1] != 0u) atomicAdd(&s64, 1); }
    if (threadIdx.x < 192) {
        int i = (threadIdx.x / 3) * 4 + 1 + (threadIdx.x % 3);
        if (mb[i] != 0) atomicAdd(&s32, 1);
    }
    __syncthreads();
    f64 = (s64 < 8);
    fm32 = (s32 < 8);
}

__device__ __forceinline__ int rd_idx2(const void* p, long long i, bool f64) {
    return f64 ? (int)((const long long*)p)[i] : ((const int*)p)[i];
}
__device__ __forceinline__ int rd_mask2(const void* p, int i, bool fm32) {
    return fm32 ? (((const int*)p)[i] != 0) : (int)((const unsigned char*)p)[i];
}

// ---------------- L0: degree + bucket counting + weight packing ----------
__global__ void k_deg2(const void* __restrict__ idx, const void* __restrict__ mask,
                       const float* __restrict__ selfw, const float* __restrict__ relw) {
    bool f64, fm32;
    detect_flags(idx, mask, f64, fm32);

    // pack weights: g_Bh[(w*64 + i)*128 + n] = pack(W[2i][n], W[2i+1][n])
    long long gid = ((long long)(blockIdx.y * gridDim.x + blockIdx.x)) * blockDim.x
                    + threadIdx.x;
    if (gid < (long long)NW * 64 * CH) {
        int j = (int)gid;
        int wi = j / (64 * CH);
        int r  = j % (64 * CH);
        int i2 = r / CH, n = r % CH;
        const float* W = (wi == 0) ? selfw : relw + (size_t)(wi - 1) * CH * CH;
        g_Bh[j] = pack_h2(W[(2 * i2) * CH + n], W[(2 * i2 + 1) * CH + n]);
    }

    int e = blockIdx.x * blockDim.x + threadIdx.x;
    int rel = blockIdx.y;
    if (e >= N_EDGES) return;
    if (!rd_mask2(mask, rel * N_EDGES + e, fm32)) return;
    int dst = rd_idx2(idx, (long long)rel * 2 * N_EDGES + N_EDGES + e, f64);
    atomicAdd(&g_deg[rel * N_NODES + dst], 1);
    int key = ((dst >> 6) * N_REL + rel) * 4 + ((dst >> 4) & 3);
    atomicAdd(&g_bcnt[key], 1);
}

// ---------------- L1: single-launch scan (parallel lookback) + invdeg ----
__global__ void k_scanall() {
    __shared__ int sh[1024];
    __shared__ int sred[128];
    int b = blockIdx.x;
    int i = b * 1024 + threadIdx.x;
    int v = (i < NBK) ? g_bcnt[i] : 0;
    sh[threadIdx.x] = v;
    __syncthreads();
    for (int off = 1; off < 1024; off <<= 1) {
        int t = (threadIdx.x >= off) ? sh[threadIdx.x - off] : 0;
        __syncthreads();
        sh[threadIdx.x] += t;
        __syncthreads();
    }
    int excl = sh[threadIdx.x] - v;

    if (threadIdx.x == 1023) {
        g_bsum[b] = sh[1023];
        __threadfence();
        atomicExch(&g_sflag[b], 1);
    }
    if (threadIdx.x < 128) {
        int part = 0;
        if ((int)threadIdx.x < b) {
            while (atomicAdd(&g_sflag[threadIdx.x], 0) == 0) { }
            part = g_bsum[threadIdx.x];
        }
        sred[threadIdx.x] = part;
    }
    __syncthreads();
    for (int off = 64; off > 0; off >>= 1) {
        if (threadIdx.x < (unsigned)off) sred[threadIdx.x] += sred[threadIdx.x + off];
        __syncthreads();
    }
    int spref = sred[0];

    if (i < NBK) {
        int o = excl + spref;
        g_boff[i] = o;
        g_bfill[i] = o;
        g_bcnt[i] = 0;                         // self-clean for next replay
    }
    if (b == NSB - 1 && threadIdx.x == 1023)
        g_boff[NBK] = spref + sh[1023];

    for (int j = i; j < N_REL * N_NODES; j += NSB * 1024) {
        int d = g_deg[j];
        g_invdeg[j] = d > 0 ? 1.0f / (float)d : 0.0f;
        g_deg[j] = 0;
    }
}

// ---------------- L2: fill sorted edge meta (+ zero scan flags) ----------
__global__ void k_fill2(const void* __restrict__ idx, const void* __restrict__ mask) {
    bool f64, fm32;
    detect_flags(idx, mask, f64, fm32);
    if (blockIdx.x == 0 && blockIdx.y == 0 && threadIdx.x < 128)
        g_sflag[threadIdx.x] = 0;
    int e = blockIdx.x * blockDim.x + threadIdx.x;
    int rel = blockIdx.y;
    if (e >= N_EDGES) return;
    if (!rd_mask2(mask, rel * N_EDGES + e, fm32)) return;
    int src = rd_idx2(idx, (long long)rel * 2 * N_EDGES + e, f64);
    int dst = rd_idx2(idx, (long long)rel * 2 * N_EDGES + N_EDGES + e, f64);
    int key = ((dst >> 6) * N_REL + rel) * 4 + ((dst >> 4) & 3);
    int pos = atomicAdd(&g_bfill[key], 1);
    g_emeta[pos] = (unsigned)src | ((unsigned)(dst & 63) << 17);
}

// ---------------- fused kernel helpers ----------------
__device__ __forceinline__ void cp16(void* sdst, const void* gsrc) {
    unsigned s = (unsigned)__cvta_generic_to_shared(sdst);
    asm volatile("cp.async.cg.shared.global [%0], [%1], 16;\n" :: "r"(s), "l"(gsrc));
}

// B stage s (weight s>>2, k-chunk s&3): 16 i-rows x 128 u32. mma tids 0..127.
__device__ __forceinline__ void cp_stage(unsigned* sBu, int s, int tid) {
    if (s < NSTG) {
        unsigned* dB = sBu + (s & 1) * BSLOT;
        const unsigned* src0 = g_Bh + (size_t)s * 2048;
#pragma unroll
        for (int j = 0; j < 4; j++) {
            int ch = tid + 128 * j;            // 512 chunks of 16B
            int i = ch >> 5, nb = ch & 31;
            cp16(dB + i * BSU + nb * 4, src0 + i * 128 + nb * 4);
        }
    }
    asm volatile("cp.async.commit_group;\n");   // uniform group count
}

// f16 m16n8k16 over one K=32 chunk; A via ldmatrix from f16 tile, B f16x2 smem.
__device__ __forceinline__ void mma4h(float (*c)[4][4], uint32_t aBase,
                                      const unsigned* Bu, int kt, int lane) {
#pragma unroll
    for (int kk = 0; kk < 2; kk++) {
        unsigned a[4][4], b[4][2];
        uint32_t colb = (uint32_t)(kt * 32 + kk * 16 + ((lane >> 4) << 3)) * 2;
        uint32_t rowoff = (uint32_t)(lane & 15) * AROW;
#pragma unroll
        for (int mf = 0; mf < 4; mf++) {
            uint32_t addr = aBase + (uint32_t)(mf * 16) * AROW + rowoff + colb;
            asm volatile("ldmatrix.sync.aligned.m8n8.x4.shared.b16 {%0,%1,%2,%3}, [%4];"
                         : "=r"(a[mf][0]), "=r"(a[mf][1]), "=r"(a[mf][2]), "=r"(a[mf][3])
                         : "r"(addr));
        }
        int i0 = kk * 8 + (lane & 3);
#pragma unroll
        for (int nf = 0; nf < 4; nf++) {
            const unsigned* Bp = Bu + i0 * BSU + nf * 8 + (lane >> 2);
            b[nf][0] = Bp[0];
            b[nf][1] = Bp[4 * BSU];
        }
#pragma unroll
        for (int mf = 0; mf < 4; mf++)
#pragma unroll
            for (int nf = 0; nf < 4; nf++)
                asm volatile(
                    "mma.sync.aligned.m16n8k16.row.col.f32.f16.f16.f32 "
                    "{%0,%1,%2,%3},{%4,%5,%6,%7},{%8,%9},{%0,%1,%2,%3};\n"
                    : "+f"(c[mf][nf][0]), "+f"(c[mf][nf][1]),
                      "+f"(c[mf][nf][2]), "+f"(c[mf][nf][3])
                    : "r"(a[mf][0]), "r"(a[mf][1]), "r"(a[mf][2]), "r"(a[mf][3]),
                      "r"(b[nf][0]), "r"(b[nf][1]));
    }
}

// gather warp gwid: rows [gwid*16,+16) of hF = sum x[src]*invdeg (R14 MLP-8 code)
__device__ __forceinline__ void gather_rel(const float* __restrict__ x, float* hb,
                                           int tile, int rel, int gwid, int lane) {
    float4 z = make_float4(0.f, 0.f, 0.f, 0.f);
    int r0 = gwid * 16;
#pragma unroll
    for (int r = 0; r < 16; r++)
        ((float4*)(hb + (r0 + r) * HS))[lane] = z;

    int key = (tile * N_REL + rel) * 4 + gwid;
    int beg = g_boff[key], end = g_boff[key + 1];
    const float* vd = g_invdeg + rel * N_NODES + tile * TM;
    for (int base = beg; base < end; base += 32) {
        unsigned m = 0;
        if (base + lane < end) m = g_emeta[base + lane];
        int n = min(32, end - base);
        int j = 0;
        for (; j + 8 <= n; j += 8) {
            int dl[8], sn[8];
            float sc[8];
            float4 v[8];
#pragma unroll
            for (int t = 0; t < 8; t++) {
                unsigned u = __shfl_sync(0xffffffffu, m, j + t);
                sn[t] = (int)(u & 0x1FFFFu);
                dl[t] = (int)(u >> 17);
            }
#pragma unroll
            for (int t = 0; t < 8; t++) sc[t] = __ldg(vd + dl[t]);
#pragma unroll
            for (int t = 0; t < 8; t++)
                v[t] = __ldg((const float4*)(x + (size_t)sn[t] * CH) + lane);
#pragma unroll
            for (int t = 0; t < 8; t++) {
                float4* hp = (float4*)(hb + dl[t] * HS) + lane;
                float4 hv = *hp;
                hv.x += v[t].x * sc[t]; hv.y += v[t].y * sc[t];
                hv.z += v[t].z * sc[t]; hv.w += v[t].w * sc[t];
                *hp = hv;
            }
        }
        for (; j + 4 <= n; j += 4) {
            int dl[4], sn[4];
            float sc[4];
            float4 v[4];
#pragma unroll
            for (int t = 0; t < 4; t++) {
                unsigned u = __shfl_sync(0xffffffffu, m, j + t);
                sn[t] = (int)(u & 0x1FFFFu);
                dl[t] = (int)(u >> 17);
            }
#pragma unroll
            for (int t = 0; t < 4; t++) sc[t] = __ldg(vd + dl[t]);
#pragma unroll
            for (int t = 0; t < 4; t++)
                v[t] = __ldg((const float4*)(x + (size_t)sn[t] * CH) + lane);
#pragma unroll
            for (int t = 0; t < 4; t++) {
                float4* hp = (float4*)(hb + dl[t] * HS) + lane;
                float4 hv = *hp;
                hv.x += v[t].x * sc[t]; hv.y += v[t].y * sc[t];
                hv.z += v[t].z * sc[t]; hv.w += v[t].w * sc[t];
                *hp = hv;
            }
        }
        for (; j < n; j++) {
            unsigned u = __shfl_sync(0xffffffffu, m, j);
            int sn = (int)(u & 0x1FFFFu);
            int dl = (int)(u >> 17);
            float s = __ldg(vd + dl);
            float4 v = __ldg((const float4*)(x + (size_t)sn * CH) + lane);
            float4* hp = (float4*)(hb + dl * HS) + lane;
            float4 hv = *hp;
            hv.x += v.x * s; hv.y += v.y * s; hv.z += v.z * s; hv.w += v.w * s;
            *hp = hv;
        }
    }
}

// convert 16 f32 rows of hF -> f16 tile rows (one pass, conflict-free)
__device__ __forceinline__ void convert_rows(const float* hF, char* hAhBuf,
                                             int gwid, int lane) {
    int r0 = gwid * 16;
#pragma unroll
    for (int r = 0; r < 16; r++) {
        float4 v = ((const float4*)(hF + (r0 + r) * HS))[lane];
        uint2 p;
        p.x = pack_h2(v.x, v.y);
        p.y = pack_h2(v.z, v.w);
        ((uint2*)(hAhBuf + (size_t)(r0 + r) * AROW))[lane] = p;
    }
}

// ---------------- fused: warps 0-3 mma, 4-7 gather+convert, 2 CTA/SM -----
__global__ __launch_bounds__(256, 2) void k_fused(const float* __restrict__ x,
                                                  float* __restrict__ out) {
    extern __shared__ float sm[];
    float* hF = sm;                                   // f32 gather scratch
    char* hAh = (char*)(sm + HF_FLOATS);              // 2 f16 tile buffers
    unsigned* sBu = (unsigned*)(sm + HF_FLOATS + HAH_FLOATS);  // B ring
    int tid = threadIdx.x, wid = tid >> 5, lane = tid & 31;
    int tile = blockIdx.x, bM = tile * TM;
    bool is_mma = (wid < 4);
    uint32_t aSh = smem_u32(hAh);

    float c[4][4][4];
#pragma unroll
    for (int i = 0; i < 4; i++)
#pragma unroll
        for (int j = 0; j < 4; j++)
#pragma unroll
            for (int k = 0; k < 4; k++) c[i][j][k] = 0.f;

    if (is_mma) {
        cp_stage(sBu, 0, tid);       // preload stage 0
    } else {
        // self tile (weight 0): x rows -> f16 into hAh[0]
        int gwid = wid - 4, r0 = gwid * 16;
#pragma unroll
        for (int r = 0; r < 16; r++) {
            int rg = bM + r0 + r;
            float4 v = make_float4(0.f, 0.f, 0.f, 0.f);
            if (rg < N_NODES) v = __ldg((const float4*)(x + (size_t)rg * CH) + lane);
            uint2 p;
            p.x = pack_h2(v.x, v.y);
            p.y = pack_h2(v.z, v.w);
            ((uint2*)(hAh + (size_t)(r0 + r) * AROW))[lane] = p;
        }
    }
    __syncthreads();   // hAh[0] ready

#pragma unroll 1
    for (int w = 0; w < NW; w++) {
        if (is_mma) {
            int wn = wid;                          // 1x4 warp grid over 64x128
            uint32_t aBase = aSh + (uint32_t)(w & 1) * HAH_BYTES;
#pragma unroll 1
            for (int kt = 0; kt < 4; kt++) {
                int s = w * 4 + kt;
                asm volatile("cp.async.wait_group 0;\n");         // stage s landed
                asm volatile("bar.sync 1, 128;\n" ::: "memory");  // mma copies/reads done
                cp_stage(sBu, s + 1, tid);         // other slot: readers done at bar
                mma4h(c, aBase, sBu + (s & 1) * BSLOT + wn * 32, kt, lane);
            }
        } else if (w < NW - 1) {
            // build f16 tile for relation w into hAh[(w+1)&1] while mma chews hAh[w&1]
            int gwid = wid - 4;
            gather_rel(x, hF, tile, w, gwid, lane);
            convert_rows(hF, hAh + (size_t)((w + 1) & 1) * HAH_BYTES, gwid, lane);
        }
        __syncthreads();   // weight boundary: next A ready, current A free
    }

    // epilogue (mma warps own the accumulators)
    if (is_mma) {
        int wn = wid;
#pragma unroll
        for (int mf = 0; mf < 4; mf++) {
            int r0 = bM + mf * 16 + (lane >> 2);
#pragma unroll
            for (int nf = 0; nf < 4; nf++) {
                int cc = wn * 32 + nf * 8 + (lane & 3) * 2;
                if (r0 < N_NODES)
                    *(float2*)(out + (size_t)r0 * CH + cc) =
                        make_float2(c[mf][nf][0], c[mf][nf][1]);
                if (r0 + 8 < N_NODES)
                    *(float2*)(out + (size_t)(r0 + 8) * CH + cc) =
                        make_float2(c[mf][nf][2], c[mf][nf][3]);
            }
        }
    }
}

// ---------------- launch: deg(0) scanall(1) fill(2) fused(3) -------------
extern "C" void kernel_launch(void* const* d_in, const int* in_sizes, int n_in,
                              void* d_out, int out_size) {
    const float* x     = (const float*)d_in[0];
    const void*  idx   = d_in[1];
    const void*  mask  = d_in[2];
    const float* selfw = (const float*)d_in[3];
    const float* relw  = (const float*)d_in[4];
    float* out = (float*)d_out;

    static int init = 0;
    size_t smem = SMEM_FLOATS * sizeof(float);   // 86016 B
    if (!init) {
        cudaFuncSetAttribute(k_fused, cudaFuncAttributeMaxDynamicSharedMemorySize, (int)smem);
        init = 1;
    }

    k_deg2<<<dim3((N_EDGES + 255) / 256, N_REL), 256>>>(idx, mask, selfw, relw);
    k_scanall<<<NSB, 1024>>>();
    k_fill2<<<dim3((N_EDGES + 255) / 256, N_REL), 256>>>(idx, mask);
    k_fused<<<NT, 256, smem>>>(x, out);
}